// round 1
// baseline (speedup 1.0000x reference)
#include <cuda_runtime.h>

#define NNET   722
#define CAMD   10
#define INDIM  11
#define HD     10
#define LODD   6

#define NT     32      // networks per block
#define WS     297     // smem stride per network (gcd(297%32,32)=1 -> conflict-free)
#define BT     4       // batch elements per thread
#define BSUB   8       // 256 threads / 32 lanes
#define BTILE  256     // batch per block

// smem layout per network (stride WS):
//   [0,110)   W1 (i*10+h)
//   [110,120) b1
//   [120,220) W2 (h*10+k)
//   [220,230) b2
//   [230,290) W3 (h*6+o)
//   [290,296) b3

__global__ __launch_bounds__(256, 2)
void grouped_mlp_kernel(const float* __restrict__ prior,
                        const float* __restrict__ camera,
                        const float* __restrict__ W1, const float* __restrict__ b1,
                        const float* __restrict__ W2, const float* __restrict__ b2,
                        const float* __restrict__ W3, const float* __restrict__ b3,
                        float* __restrict__ out)
{
    __shared__ float ws[NT * WS];

    const int tid    = threadIdx.x;
    const int n0     = blockIdx.x * NT;
    const int b_base = blockIdx.y * BTILE;

    // ---- cooperative weight staging (coalesced per-array) ----
    for (int f = tid; f < NT * 110; f += 256) {
        int nl = f / 110, idx = f - nl * 110;
        if (n0 + nl < NNET) ws[nl * WS + idx] = W1[(n0 + nl) * 110 + idx];
    }
    for (int f = tid; f < NT * 10; f += 256) {
        int nl = f / 10, idx = f - nl * 10;
        if (n0 + nl < NNET) ws[nl * WS + 110 + idx] = b1[(n0 + nl) * 10 + idx];
    }
    for (int f = tid; f < NT * 100; f += 256) {
        int nl = f / 100, idx = f - nl * 100;
        if (n0 + nl < NNET) ws[nl * WS + 120 + idx] = W2[(n0 + nl) * 100 + idx];
    }
    for (int f = tid; f < NT * 10; f += 256) {
        int nl = f / 10, idx = f - nl * 10;
        if (n0 + nl < NNET) ws[nl * WS + 220 + idx] = b2[(n0 + nl) * 10 + idx];
    }
    for (int f = tid; f < NT * 60; f += 256) {
        int nl = f / 60, idx = f - nl * 60;
        if (n0 + nl < NNET) ws[nl * WS + 230 + idx] = W3[(n0 + nl) * 60 + idx];
    }
    for (int f = tid; f < NT * 6; f += 256) {
        int nl = f / 6, idx = f - nl * 6;
        if (n0 + nl < NNET) ws[nl * WS + 290 + idx] = b3[(n0 + nl) * 6 + idx];
    }
    __syncthreads();

    const int nl   = tid & 31;         // lane -> network (coalesced prior/out)
    const int n    = n0 + nl;
    const int bsub = tid >> 5;
    const float* __restrict__ w = &ws[nl * WS];

    if (n >= NNET) return;             // tail tile: no more barriers below

    #pragma unroll 1
    for (int it = 0; it < BTILE / (BSUB * BT); ++it) {
        const int b0 = b_base + (it * BSUB + bsub) * BT;

        // ---------------- layer 1: 11 -> 10 ----------------
        float acc[BT][HD];
        #pragma unroll
        for (int h = 0; h < HD; ++h) {
            const float bb = w[110 + h];
            #pragma unroll
            for (int t = 0; t < BT; ++t) acc[t][h] = bb;
        }
        {   // i = 0 : prior_lod (coalesced across lanes)
            float xv[BT];
            #pragma unroll
            for (int t = 0; t < BT; ++t)
                xv[t] = prior[(size_t)(b0 + t) * NNET + n];
            #pragma unroll
            for (int h = 0; h < HD; ++h) {
                const float wv = w[h];
                #pragma unroll
                for (int t = 0; t < BT; ++t) acc[t][h] = fmaf(xv[t], wv, acc[t][h]);
            }
        }
        #pragma unroll
        for (int i = 1; i < INDIM; ++i) {   // camera features (warp-uniform broadcast LDG)
            float xv[BT];
            #pragma unroll
            for (int t = 0; t < BT; ++t)
                xv[t] = __ldg(&camera[(b0 + t) * CAMD + (i - 1)]);
            #pragma unroll
            for (int h = 0; h < HD; ++h) {
                const float wv = w[i * 10 + h];
                #pragma unroll
                for (int t = 0; t < BT; ++t) acc[t][h] = fmaf(xv[t], wv, acc[t][h]);
            }
        }
        // relu (in place: acc becomes h1)
        #pragma unroll
        for (int t = 0; t < BT; ++t)
            #pragma unroll
            for (int h = 0; h < HD; ++h) acc[t][h] = fmaxf(acc[t][h], 0.0f);

        // ---------------- layer 2: 10 -> 10 ----------------
        float acc2[BT][HD];
        #pragma unroll
        for (int k = 0; k < HD; ++k) {
            const float bb = w[220 + k];
            #pragma unroll
            for (int t = 0; t < BT; ++t) acc2[t][k] = bb;
        }
        #pragma unroll
        for (int h = 0; h < HD; ++h) {
            #pragma unroll
            for (int k = 0; k < HD; ++k) {
                const float wv = w[120 + h * 10 + k];
                #pragma unroll
                for (int t = 0; t < BT; ++t) acc2[t][k] = fmaf(acc[t][h], wv, acc2[t][k]);
            }
        }
        // relu (in place: acc2 becomes h2)
        #pragma unroll
        for (int t = 0; t < BT; ++t)
            #pragma unroll
            for (int k = 0; k < HD; ++k) acc2[t][k] = fmaxf(acc2[t][k], 0.0f);

        // ---------------- layer 3: 10 -> 6 ----------------
        float acc3[BT][LODD];
        #pragma unroll
        for (int o = 0; o < LODD; ++o) {
            const float bb = w[290 + o];
            #pragma unroll
            for (int t = 0; t < BT; ++t) acc3[t][o] = bb;
        }
        #pragma unroll
        for (int h = 0; h < HD; ++h) {
            #pragma unroll
            for (int o = 0; o < LODD; ++o) {
                const float wv = w[230 + h * 6 + o];
                #pragma unroll
                for (int t = 0; t < BT; ++t) acc3[t][o] = fmaf(acc2[t][h], wv, acc3[t][o]);
            }
        }

        // ---------------- store (lane-consecutive n -> contiguous 768B/warp per o) ----
        #pragma unroll
        for (int t = 0; t < BT; ++t) {
            float* __restrict__ op = out + ((size_t)(b0 + t) * NNET + n) * LODD;
            #pragma unroll
            for (int o = 0; o < LODD; ++o) op[o] = acc3[t][o];
        }
    }
}

extern "C" void kernel_launch(void* const* d_in, const int* in_sizes, int n_in,
                              void* d_out, int out_size)
{
    const float* prior  = (const float*)d_in[0];
    const float* camera = (const float*)d_in[1];
    const float* W1     = (const float*)d_in[2];
    const float* b1     = (const float*)d_in[3];
    const float* W2     = (const float*)d_in[4];
    const float* b2     = (const float*)d_in[5];
    const float* W3     = (const float*)d_in[6];
    const float* b3     = (const float*)d_in[7];
    float* out          = (float*)d_out;

    const int B = in_sizes[1] / CAMD;   // 8192
    dim3 grid((NNET + NT - 1) / NT, B / BTILE);   // 23 x 32
    grouped_mlp_kernel<<<grid, 256>>>(prior, camera, W1, b1, W2, b2, W3, b3, out);
}

// round 2
// speedup vs baseline: 1.1737x; 1.1737x over previous
#include <cuda_runtime.h>

#define NNET   722
#define CAMD   10
#define INDIM  11
#define HD     10
#define LODD   6

#define NT     32      // networks per block (lane -> network)
#define WS     298     // even stride: 8B-aligned per-lane bases; 64-bit conflict-free
#define BT     4       // batch elements per thread
#define BSUB   8       // 256 threads / 32 lanes
#define BTILE  256     // batch per block

// smem layout per network (stride WS, all pair-offsets even):
//   [0,110)   W1 (i*10+h)
//   [110,120) b1
//   [120,220) W2 (h*10+k)
//   [220,230) b2
//   [230,290) W3 (h*6+o)
//   [290,296) b3

typedef unsigned long long u64;

__device__ __forceinline__ u64 fma2(u64 a, u64 b, u64 c) {
    u64 d;
    asm("fma.rn.f32x2 %0, %1, %2, %3;" : "=l"(d) : "l"(a), "l"(b), "l"(c));
    return d;
}
__device__ __forceinline__ u64 bcast2(float x) {      // {x, x}
    u64 d;
    asm("mov.b64 %0, {%1, %1};" : "=l"(d) : "f"(x));
    return d;
}
__device__ __forceinline__ void unpack2(u64 v, float& lo, float& hi) {
    asm("mov.b64 {%0, %1}, %2;" : "=f"(lo), "=f"(hi) : "l"(v));
}
__device__ __forceinline__ u64 lds64(const float* p) {  // adjacent weight pair
    return *reinterpret_cast<const u64*>(p);
}

__global__ __launch_bounds__(256, 2)
void grouped_mlp_kernel(const float* __restrict__ prior,
                        const float* __restrict__ camera,
                        const float* __restrict__ W1, const float* __restrict__ b1,
                        const float* __restrict__ W2, const float* __restrict__ b2,
                        const float* __restrict__ W3, const float* __restrict__ b3,
                        float* __restrict__ out)
{
    __shared__ __align__(16) float ws[NT * WS];

    const int tid    = threadIdx.x;
    const int n0     = blockIdx.x * NT;
    const int b_base = blockIdx.y * BTILE;

    // ---- cooperative weight staging ----
    for (int f = tid; f < NT * 110; f += 256) {
        int nl = f / 110, idx = f - nl * 110;
        if (n0 + nl < NNET) ws[nl * WS + idx] = W1[(n0 + nl) * 110 + idx];
    }
    for (int f = tid; f < NT * 10; f += 256) {
        int nl = f / 10, idx = f - nl * 10;
        if (n0 + nl < NNET) ws[nl * WS + 110 + idx] = b1[(n0 + nl) * 10 + idx];
    }
    for (int f = tid; f < NT * 100; f += 256) {
        int nl = f / 100, idx = f - nl * 100;
        if (n0 + nl < NNET) ws[nl * WS + 120 + idx] = W2[(n0 + nl) * 100 + idx];
    }
    for (int f = tid; f < NT * 10; f += 256) {
        int nl = f / 10, idx = f - nl * 10;
        if (n0 + nl < NNET) ws[nl * WS + 220 + idx] = b2[(n0 + nl) * 10 + idx];
    }
    for (int f = tid; f < NT * 60; f += 256) {
        int nl = f / 60, idx = f - nl * 60;
        if (n0 + nl < NNET) ws[nl * WS + 230 + idx] = W3[(n0 + nl) * 60 + idx];
    }
    for (int f = tid; f < NT * 6; f += 256) {
        int nl = f / 6, idx = f - nl * 6;
        if (n0 + nl < NNET) ws[nl * WS + 290 + idx] = b3[(n0 + nl) * 6 + idx];
    }
    __syncthreads();

    const int nl   = tid & 31;
    const int n    = n0 + nl;
    const int bsub = tid >> 5;
    const float* __restrict__ w = &ws[nl * WS];

    if (n >= NNET) return;   // tail tile; no more barriers below

    #pragma unroll 1
    for (int it = 0; it < BTILE / (BSUB * BT); ++it) {
        const int b0 = b_base + (it * BSUB + bsub) * BT;

        // ---------------- layer 1: 11 -> 10 (h-pairs packed) ----------------
        u64 acc[BT][HD / 2];
        {   // i = 0 : prior (coalesced LDG), fold bias as the fma addend
            u64 xp[BT];
            #pragma unroll
            for (int t = 0; t < BT; ++t)
                xp[t] = bcast2(prior[(size_t)(b0 + t) * NNET + n]);
            #pragma unroll
            for (int j = 0; j < HD / 2; ++j) {
                const u64 wp = lds64(&w[2 * j]);          // W1[0][2j..2j+1]
                const u64 bp = lds64(&w[110 + 2 * j]);    // b1 pair
                #pragma unroll
                for (int t = 0; t < BT; ++t) acc[t][j] = fma2(xp[t], wp, bp);
            }
        }
        #pragma unroll
        for (int i = 1; i < INDIM; ++i) {   // camera (warp-uniform broadcast LDG)
            u64 xp[BT];
            #pragma unroll
            for (int t = 0; t < BT; ++t)
                xp[t] = bcast2(__ldg(&camera[(b0 + t) * CAMD + (i - 1)]));
            #pragma unroll
            for (int j = 0; j < HD / 2; ++j) {
                const u64 wp = lds64(&w[i * 10 + 2 * j]);
                #pragma unroll
                for (int t = 0; t < BT; ++t) acc[t][j] = fma2(xp[t], wp, acc[t][j]);
            }
        }
        // relu -> h1 scalars
        float h1[BT][HD];
        #pragma unroll
        for (int t = 0; t < BT; ++t)
            #pragma unroll
            for (int j = 0; j < HD / 2; ++j) {
                float lo, hi; unpack2(acc[t][j], lo, hi);
                h1[t][2 * j]     = fmaxf(lo, 0.0f);
                h1[t][2 * j + 1] = fmaxf(hi, 0.0f);
            }

        // ---------------- layer 2: 10 -> 10 (k-pairs packed) ----------------
        u64 acc2[BT][HD / 2];
        #pragma unroll
        for (int j = 0; j < HD / 2; ++j) {                // h = 0, bias folded
            const u64 wp = lds64(&w[120 + 2 * j]);
            const u64 bp = lds64(&w[220 + 2 * j]);
            #pragma unroll
            for (int t = 0; t < BT; ++t) acc2[t][j] = fma2(bcast2(h1[t][0]), wp, bp);
        }
        #pragma unroll
        for (int h = 1; h < HD; ++h) {
            u64 xp[BT];
            #pragma unroll
            for (int t = 0; t < BT; ++t) xp[t] = bcast2(h1[t][h]);
            #pragma unroll
            for (int j = 0; j < HD / 2; ++j) {
                const u64 wp = lds64(&w[120 + h * 10 + 2 * j]);
                #pragma unroll
                for (int t = 0; t < BT; ++t) acc2[t][j] = fma2(xp[t], wp, acc2[t][j]);
            }
        }
        // relu -> h2 scalars
        float h2[BT][HD];
        #pragma unroll
        for (int t = 0; t < BT; ++t)
            #pragma unroll
            for (int j = 0; j < HD / 2; ++j) {
                float lo, hi; unpack2(acc2[t][j], lo, hi);
                h2[t][2 * j]     = fmaxf(lo, 0.0f);
                h2[t][2 * j + 1] = fmaxf(hi, 0.0f);
            }

        // ---------------- layer 3: 10 -> 6 (o-pairs packed) ----------------
        u64 acc3[BT][LODD / 2];
        #pragma unroll
        for (int j = 0; j < LODD / 2; ++j) {              // h = 0, bias folded
            const u64 wp = lds64(&w[230 + 2 * j]);
            const u64 bp = lds64(&w[290 + 2 * j]);
            #pragma unroll
            for (int t = 0; t < BT; ++t) acc3[t][j] = fma2(bcast2(h2[t][0]), wp, bp);
        }
        #pragma unroll
        for (int h = 1; h < HD; ++h) {
            u64 xp[BT];
            #pragma unroll
            for (int t = 0; t < BT; ++t) xp[t] = bcast2(h2[t][h]);
            #pragma unroll
            for (int j = 0; j < LODD / 2; ++j) {
                const u64 wp = lds64(&w[230 + h * 6 + 2 * j]);
                #pragma unroll
                for (int t = 0; t < BT; ++t) acc3[t][j] = fma2(xp[t], wp, acc3[t][j]);
            }
        }

        // ---------------- packed 64-bit stores (8B-aligned: 24B stride) ----------------
        #pragma unroll
        for (int t = 0; t < BT; ++t) {
            float* __restrict__ op = out + ((size_t)(b0 + t) * NNET + n) * LODD;
            #pragma unroll
            for (int j = 0; j < LODD / 2; ++j)
                *reinterpret_cast<u64*>(op + 2 * j) = acc3[t][j];
        }
    }
}

extern "C" void kernel_launch(void* const* d_in, const int* in_sizes, int n_in,
                              void* d_out, int out_size)
{
    const float* prior  = (const float*)d_in[0];
    const float* camera = (const float*)d_in[1];
    const float* W1     = (const float*)d_in[2];
    const float* b1     = (const float*)d_in[3];
    const float* W2     = (const float*)d_in[4];
    const float* b2     = (const float*)d_in[5];
    const float* W3     = (const float*)d_in[6];
    const float* b3     = (const float*)d_in[7];
    float* out          = (float*)d_out;

    const int B = in_sizes[1] / CAMD;   // 8192
    dim3 grid((NNET + NT - 1) / NT, B / BTILE);   // 23 x 32
    grouped_mlp_kernel<<<grid, 256>>>(prior, camera, W1, b1, W2, b2, W3, b3, out);
}